// round 1
// baseline (speedup 1.0000x reference)
#include <cuda_runtime.h>
#include <math.h>

#define BB     32
#define CC     512
#define TT     1024
#define KS     13
#define RAD    6
#define TILE_C 128
#define TILE_T 32
#define NTILES (TT / TILE_T)          // 32
#define ROWS   (TILE_C + 2 * RAD)     // 140
#define SROW   36                     // padded floats per shared row (conflict-free LDS.128)
#define NTHR   128
#define THRV   0.5f
#define BETA   0.95f

__device__ __forceinline__ void cp_async_16(unsigned saddr, const void* gptr, int src_sz) {
    asm volatile("cp.async.ca.shared.global [%0], [%1], 16, %2;\n"
                 :: "r"(saddr), "l"(gptr), "r"(src_sz));
}
__device__ __forceinline__ void cp_commit() {
    asm volatile("cp.async.commit_group;\n");
}
__device__ __forceinline__ void cp_wait1() {
    asm volatile("cp.async.wait_group 1;\n");
}

__device__ __forceinline__ void load_tile(const float* __restrict__ xb,
                                          int c0, int t0, float* __restrict__ sbuf) {
    // Load ROWS x TILE_T tile (with c-halo), zero-filling out-of-range channels.
    // ROWS*8 = 1120 float4 transfers, strided over 128 threads.
    for (int i = threadIdx.x; i < ROWS * (TILE_T / 4); i += NTHR) {
        int r = i >> 3;          // 0..139
        int g = i & 7;           // float4 group within t-tile
        int ch = c0 + r - RAD;
        bool valid = ((unsigned)ch < (unsigned)CC);
        int chc = valid ? ch : 0;               // keep address in-bounds even when zero-filling
        const float* gp = xb + (size_t)chc * TT + t0 + g * 4;
        unsigned sa = (unsigned)__cvta_generic_to_shared(sbuf + r * SROW + g * 4);
        cp_async_16(sa, gp, valid ? 16 : 0);
    }
}

__global__ __launch_bounds__(NTHR, 1)
void snn_lif_kernel(const float* __restrict__ x,
                    const float* __restrict__ wp,
                    float* __restrict__ out) {
    __shared__ float sm[2][ROWS * SROW];

    const int tid = threadIdx.x;
    const int c0  = blockIdx.x * TILE_C;
    const int b   = blockIdx.y;

    const float* xb   = x   + (size_t)b * CC * TT;
    float*       outb = out + (size_t)b * CC * TT + (size_t)(c0 + tid) * TT;

    // --- Gaussian weights (computed per-thread; negligible cost) ---
    float w = wp[0];
    float sigma = 0.5f * (1.0f + 10.0f) + fminf(fmaxf(w, 1.0f), 10.0f);
    float inv2s2 = 0.5f / (sigma * sigma);
    float kw[KS];
    float ksum = 0.0f;
#pragma unroll
    for (int j = 0; j < KS; ++j) {
        float r = (float)(j - RAD);
        kw[j] = expf(-r * r * inv2s2);
        ksum += kw[j];
    }
    float kinv = 1.0f / ksum;
#pragma unroll
    for (int j = 0; j < KS; ++j) kw[j] *= kinv;

    // --- Pipelined tile loop: double-buffered cp.async ---
    load_tile(xb, c0, 0, sm[0]);
    cp_commit();

    float mem = 0.0f;
    int buf = 0;

    for (int tile = 0; tile < NTILES; ++tile) {
        if (tile + 1 < NTILES)
            load_tile(xb, c0, (tile + 1) * TILE_T, sm[buf ^ 1]);
        cp_commit();
        cp_wait1();              // tile's own group is now complete
        __syncthreads();

        const float* s = sm[buf] + tid * SROW;   // row of this thread's own channel - RAD offset handled via +j

#pragma unroll
        for (int g = 0; g < 8; ++g) {
            float4 acc = make_float4(0.f, 0.f, 0.f, 0.f);
            float4 xc;
#pragma unroll
            for (int j = 0; j < KS; ++j) {
                float4 v = *(const float4*)(s + j * SROW + g * 4);
                acc.x = fmaf(kw[j], v.x, acc.x);
                acc.y = fmaf(kw[j], v.y, acc.y);
                acc.z = fmaf(kw[j], v.z, acc.z);
                acc.w = fmaf(kw[j], v.w, acc.w);
                if (j == RAD) xc = v;
            }
            float d0 = xc.x - acc.x;
            float d1 = xc.y - acc.y;
            float d2 = xc.z - acc.z;
            float d3 = xc.w - acc.w;

            float4 spk;
            // LIF step: reset uses PREVIOUS mem; spike uses UPDATED mem (strict >)
            mem = fmaf(BETA, mem, d0) - ((mem > THRV) ? THRV : 0.0f);
            spk.x = (mem > THRV) ? 1.0f : 0.0f;
            mem = fmaf(BETA, mem, d1) - ((mem > THRV) ? THRV : 0.0f);
            spk.y = (mem > THRV) ? 1.0f : 0.0f;
            mem = fmaf(BETA, mem, d2) - ((mem > THRV) ? THRV : 0.0f);
            spk.z = (mem > THRV) ? 1.0f : 0.0f;
            mem = fmaf(BETA, mem, d3) - ((mem > THRV) ? THRV : 0.0f);
            spk.w = (mem > THRV) ? 1.0f : 0.0f;

            *(float4*)(outb + tile * TILE_T + g * 4) = spk;
        }
        __syncthreads();         // all reads of this buffer done before it is refilled
        buf ^= 1;
    }
}

extern "C" void kernel_launch(void* const* d_in, const int* in_sizes, int n_in,
                              void* d_out, int out_size) {
    const float* inp = (const float*)d_in[0];
    const float* w   = (const float*)d_in[1];
    float* out       = (float*)d_out;

    dim3 grid(CC / TILE_C, BB);   // (4, 32) = 128 CTAs
    dim3 blk(NTHR);               // 128 threads, 1 channel per thread
    snn_lif_kernel<<<grid, blk>>>(inp, w, out);
}